// round 12
// baseline (speedup 1.0000x reference)
#include <cuda_runtime.h>
#include <cstdint>

#define THREADS 256
#define ROWS    256   // rows per chunk
#define NDIM    6
#define JLEV    8
#define CHAN    64
#define GRIDB   888   // 148 SMs x 6 resident blocks: exact one-wave persistence

// ---------------------------------------------------------------------------
// LTS-capped kernel (~6300 B/cyc chip-wide L2 ceiling):
//   per-launch L2 traffic = 512MB cb-read + 512MB write + 64MB misc ~= 1.09GB
//   -> ~89-91us floor at NAT clock. Persistent grid-stride blocks remove the
//   0.8-wave tail and amortize the prologue; inner dataflow unchanged from
//   the best-measured R9 config.
// ---------------------------------------------------------------------------
__global__ __launch_bounds__(THREADS)
void fsq_quantize_kernel(const float* __restrict__ z,
                         const float* __restrict__ perc,
                         const float* __restrict__ cb,
                         float* __restrict__ out_q,      // [B,64]
                         float* __restrict__ out_idx_f,  // [B] float tail
                         int B, int nchunks)
{
    __shared__ float sz[ROWS * NDIM];     // 6 KB
    __shared__ float sp[JLEV * NDIM];     // 192 B
    __shared__ long long soff[ROWS];      // 2 KB: precomputed float-offsets

    const int tid = threadIdx.x;
    if (tid < JLEV * NDIM) sp[tid] = perc[tid];

    for (int c = blockIdx.x; c < nchunks; c += gridDim.x) {
        const long long base = (long long)c * ROWS;
        const bool full = (base + ROWS) <= (long long)B;
        const int nrows = full ? ROWS : (int)((long long)B - base);

        if (full) {
            // 1536 floats = 384 float4; chunk offset 6144B -> 16B aligned
            float4* szv = (float4*)sz;
            const float4* zv = (const float4*)(z + base * NDIM);
            szv[tid] = __ldcs(&zv[tid]);
            if (tid < 128) szv[256 + tid] = __ldcs(&zv[256 + tid]);
        } else {
            const int total = nrows * NDIM;
            for (int e = tid; e < total; e += THREADS)
                sz[e] = __ldcs(&z[base * NDIM + e]);
        }
        __syncthreads();

        if (tid < nrows) {
            int big = 0;
            #pragma unroll
            for (int i = 0; i < NDIM; i++) {
                const float v = sz[tid * NDIM + i];
                int idx = 0;
                // sorted per-dim edges: max{ j : v >= p[j] } == count j>=1
                #pragma unroll
                for (int j = 1; j < JLEV; j++)
                    idx += (v >= sp[j * NDIM + i]) ? 1 : 0;
                big |= idx << (3 * i);   // basis = 8^i
            }
            soff[tid] = (long long)big * CHAN;   // pre-scaled gather offset
            out_idx_f[base + tid] = (float)big;
        }
        __syncthreads();

        if (full) {
            // 16 lanes x float4 per row; 4096 float4 per chunk; each thread
            // does 16 vectors in 4 batches of 4 independent loads (MLP=4).
            // __ldcg: 64MB codebook never fits L1 -> skip L1 allocation.
            float4* dstb = (float4*)(out_q + base * (long long)CHAN);
            #pragma unroll
            for (int u0 = 0; u0 < 16; u0 += 4) {
                const float4* s[4];
                #pragma unroll
                for (int k = 0; k < 4; k++) {
                    const int e = (u0 + k) * THREADS + tid;
                    s[k] = (const float4*)(cb + soff[e >> 4]) + (e & 15);
                }
                float4 v0 = __ldcg(s[0]);
                float4 v1 = __ldcg(s[1]);
                float4 v2 = __ldcg(s[2]);
                float4 v3 = __ldcg(s[3]);
                __stcs(&dstb[(u0 + 0) * THREADS + tid], v0);
                __stcs(&dstb[(u0 + 1) * THREADS + tid], v1);
                __stcs(&dstb[(u0 + 2) * THREADS + tid], v2);
                __stcs(&dstb[(u0 + 3) * THREADS + tid], v3);
            }
        } else {
            const int totalv = nrows * (CHAN / 4);
            for (int e = tid; e < totalv; e += THREADS) {
                const int r = e >> 4;
                const int cc = e & 15;
                const float4 v = __ldcg((const float4*)(cb + soff[r]) + cc);
                __stcs((float4*)(out_q + (base + r) * (long long)CHAN) + cc, v);
            }
        }
        __syncthreads();   // protect sz/soff before next chunk overwrites
    }
}

extern "C" void kernel_launch(void* const* d_in, const int* in_sizes, int n_in,
                              void* d_out, int out_size)
{
    const float* z    = (const float*)d_in[0];   // [B,6]
    const float* perc = (const float*)d_in[1];   // [8,6]
    const float* cb   = (const float*)d_in[2];   // [262144,64]
    const int B = in_sizes[0] / NDIM;

    const long long nq = (long long)B * CHAN;

    float* out_q     = (float*)d_out;
    float* out_idx_f = (float*)d_out + nq;   // confirmed layout: [B*64 | B]
    (void)out_size;

    const int nchunks = (B + ROWS - 1) / ROWS;
    const int grid = nchunks < GRIDB ? nchunks : GRIDB;
    fsq_quantize_kernel<<<grid, THREADS>>>(z, perc, cb, out_q, out_idx_f,
                                           B, nchunks);
}

// round 13
// speedup vs baseline: 1.1966x; 1.1966x over previous
#include <cuda_runtime.h>
#include <cstdint>

#define THREADS 256
#define ROWS    256   // rows per block
#define NDIM    6
#define JLEV    8
#define CHAN    64

// ---------------------------------------------------------------------------
// LTS-capped kernel (~6300 B/cyc chip-wide L2 ceiling ~= 12 TB/s @ NAT):
//   per-launch L2 traffic = 512MB cb-read(hit) + 512MB write + ~70MB misc.
// R9 dataflow kept byte-identical; the only change: big_index is computed
// with a warp-local row mapping and distributed via __shfl_sync, removing
// the second __syncthreads and the smem offset round-trip. Warps drain
// independently through the gather phase.
//   lane l of warp w computes row 16*(l>>1) + 2w + (l&1);
//   gather iter u, lane l needs row 16u + 2w + (l>>4)  == lane 2u + (l>>4).
// ---------------------------------------------------------------------------
__global__ __launch_bounds__(THREADS)
void fsq_quantize_kernel(const float* __restrict__ z,
                         const float* __restrict__ perc,
                         const float* __restrict__ cb,
                         float* __restrict__ out_q,      // [B,64]
                         float* __restrict__ out_idx_f,  // [B] float tail
                         int B)
{
    __shared__ float sz[ROWS * NDIM];     // 6 KB
    __shared__ float sp[JLEV * NDIM];     // 192 B
    __shared__ int   sidx[ROWS];          // tail path only

    const int tid = threadIdx.x;
    const int w   = tid >> 5;
    const int l   = tid & 31;
    const long long base = (long long)blockIdx.x * ROWS;
    const bool full = (base + ROWS) <= (long long)B;
    const int nrows = full ? ROWS : (int)((long long)B - base);
    if (nrows <= 0) return;

    if (tid < JLEV * NDIM) sp[tid] = perc[tid];

    if (full) {
        // 1536 floats = 384 float4; block offset 6144B -> 16B aligned
        float4* szv = (float4*)sz;
        const float4* zv = (const float4*)(z + base * NDIM);
        szv[tid] = __ldcs(&zv[tid]);
        if (tid < 128) szv[256 + tid] = __ldcs(&zv[256 + tid]);
    } else {
        const int total = nrows * NDIM;
        for (int e = tid; e < total; e += THREADS)
            sz[e] = __ldcs(&z[base * NDIM + e]);
    }
    __syncthreads();   // only block-wide barrier on the full path

    if (full) {
        // warp-local row assignment: lane l computes row 16*(l>>1)+2w+(l&1)
        const int myrow = 16 * (l >> 1) + 2 * w + (l & 1);
        int big = 0;
        #pragma unroll
        for (int i = 0; i < NDIM; i++) {
            const float v = sz[myrow * NDIM + i];
            int idx = 0;
            // sorted per-dim edges: max{ j : v >= p[j] } == count over j>=1
            #pragma unroll
            for (int j = 1; j < JLEV; j++)
                idx += (v >= sp[j * NDIM + i]) ? 1 : 0;
            big |= idx << (3 * i);   // basis = 8^i
        }
        out_idx_f[base + myrow] = (float)big;

        // gather: 16 lanes x float4 per row; 16 vectors per thread in 4
        // batches of 4 independent loads (MLP=4). __ldcg: 64MB codebook
        // never fits L1. Row index arrives by shuffle -> no barrier needed.
        float4* dstb = (float4*)(out_q + base * (long long)CHAN);
        const int h = l >> 4;    // which of the warp's 2 rows per iter
        const int col = l & 15;
        #pragma unroll
        for (int u0 = 0; u0 < 16; u0 += 4) {
            const float4* s[4];
            #pragma unroll
            for (int k = 0; k < 4; k++) {
                const int rb = __shfl_sync(0xffffffffu, big, 2 * (u0 + k) + h);
                s[k] = (const float4*)(cb + (long long)rb * CHAN) + col;
            }
            float4 v0 = __ldcg(s[0]);
            float4 v1 = __ldcg(s[1]);
            float4 v2 = __ldcg(s[2]);
            float4 v3 = __ldcg(s[3]);
            __stcs(&dstb[(u0 + 0) * THREADS + tid], v0);
            __stcs(&dstb[(u0 + 1) * THREADS + tid], v1);
            __stcs(&dstb[(u0 + 2) * THREADS + tid], v2);
            __stcs(&dstb[(u0 + 3) * THREADS + tid], v3);
        }
    } else {
        // tail chunk (at most one block): original smem-indexed path
        if (tid < nrows) {
            int big = 0;
            #pragma unroll
            for (int i = 0; i < NDIM; i++) {
                const float v = sz[tid * NDIM + i];
                int idx = 0;
                #pragma unroll
                for (int j = 1; j < JLEV; j++)
                    idx += (v >= sp[j * NDIM + i]) ? 1 : 0;
                big |= idx << (3 * i);
            }
            sidx[tid] = big;
            out_idx_f[base + tid] = (float)big;
        }
        __syncthreads();

        const int totalv = nrows * (CHAN / 4);
        for (int e = tid; e < totalv; e += THREADS) {
            const int r = e >> 4;
            const int c = e & 15;
            const float4 v =
                __ldcg((const float4*)(cb + (long long)sidx[r] * CHAN) + c);
            __stcs((float4*)(out_q + (base + r) * (long long)CHAN) + c, v);
        }
    }
}

extern "C" void kernel_launch(void* const* d_in, const int* in_sizes, int n_in,
                              void* d_out, int out_size)
{
    const float* z    = (const float*)d_in[0];   // [B,6]
    const float* perc = (const float*)d_in[1];   // [8,6]
    const float* cb   = (const float*)d_in[2];   // [262144,64]
    const int B = in_sizes[0] / NDIM;

    const long long nq = (long long)B * CHAN;

    float* out_q     = (float*)d_out;
    float* out_idx_f = (float*)d_out + nq;   // confirmed layout: [B*64 | B]
    (void)out_size;

    const int blocks = (B + ROWS - 1) / ROWS;
    fsq_quantize_kernel<<<blocks, THREADS>>>(z, perc, cb, out_q, out_idx_f, B);
}